// round 1
// baseline (speedup 1.0000x reference)
#include <cuda_runtime.h>

#define B_SZ 8192
#define K_SZ 25
#define L_SZ 25
#define NTHREADS 128
#define BN_EPS 1e-5f

typedef unsigned long long u64;

__device__ float g_scale[L_SZ];
__device__ float g_shift[L_SZ];

// ---------- packed f32x2 helpers ----------
__device__ __forceinline__ u64 pack2(float a, float b) {
    u64 r;
    asm("mov.b64 %0, {%1, %2};" : "=l"(r) : "r"(__float_as_uint(a)), "r"(__float_as_uint(b)));
    return r;
}
__device__ __forceinline__ u64 dup2(float a) { return pack2(a, a); }
__device__ __forceinline__ float2 unpack2(u64 v) {
    unsigned lo, hi;
    asm("mov.b64 {%0, %1}, %2;" : "=r"(lo), "=r"(hi) : "l"(v));
    return make_float2(__uint_as_float(lo), __uint_as_float(hi));
}
// FFMA2: two fp32 FMAs in one instruction (only reachable via PTX fma.rn.f32x2)
__device__ __forceinline__ u64 ffma2(u64 a, u64 b, u64 c) {
    u64 d;
    asm("fma.rn.f32x2 %0, %1, %2, %3;" : "=l"(d) : "l"(a), "l"(b), "l"(c));
    return d;
}
__device__ __forceinline__ u64 relu2(u64 v) {
    float2 f = unpack2(v);
    return pack2(fmaxf(f.x, 0.f), fmaxf(f.y, 0.f));
}

// ---------- kernel 1: BatchNorm statistics per column ----------
__global__ void bn_stats_kernel(const float* __restrict__ x,
                                const float* __restrict__ gamma,
                                const float* __restrict__ bn_bias) {
    const int l = blockIdx.x;
    const int tid = threadIdx.x;
    float s = 0.f, q = 0.f;
    for (int b = tid; b < B_SZ; b += 256) {
        float v = x[b * L_SZ + l];
        s += v;
        q = fmaf(v, v, q);
    }
    // warp reduce
    #pragma unroll
    for (int o = 16; o > 0; o >>= 1) {
        s += __shfl_down_sync(0xFFFFFFFFu, s, o);
        q += __shfl_down_sync(0xFFFFFFFFu, q, o);
    }
    __shared__ float ss[8], sq[8];
    const int w = tid >> 5, ln = tid & 31;
    if (ln == 0) { ss[w] = s; sq[w] = q; }
    __syncthreads();
    if (tid == 0) {
        float S = 0.f, Q = 0.f;
        #pragma unroll
        for (int i = 0; i < 8; ++i) { S += ss[i]; Q += sq[i]; }
        float mean = S / (float)B_SZ;
        float var  = Q / (float)B_SZ - mean * mean;
        float rstd = rsqrtf(var + BN_EPS);
        float sc = gamma[l] * rstd;
        g_scale[l] = sc;
        g_shift[l] = bn_bias[l] - mean * sc;
    }
}

// ---------- kernel 2: fused tiny-MLP ensemble ----------
__global__ void __launch_bounds__(NTHREADS) mlp_kernel(
    const float* __restrict__ x,
    const float* __restrict__ W1, const float* __restrict__ b1,
    const float* __restrict__ W2, const float* __restrict__ b2,
    const float* __restrict__ W3, const float* __restrict__ b3,
    const float* __restrict__ W4, const float* __restrict__ b4,
    const float* __restrict__ alpha, const float* __restrict__ beta,
    float* __restrict__ out)
{
    // weights duplicated as {w,w} pairs so each LDS.64/128 feeds FFMA2 directly
    __shared__ __align__(16) u64 sW1[L_SZ][8];
    __shared__ __align__(16) u64 sB1[L_SZ][8];
    __shared__ __align__(16) u64 sW2[L_SZ][8][8];
    __shared__ __align__(16) u64 sB2[L_SZ][8];
    __shared__ __align__(16) u64 sW3[L_SZ][6][8];
    __shared__ u64 sB3[L_SZ][6];
    __shared__ u64 sW4[L_SZ][6];
    __shared__ u64 sB4[L_SZ];
    __shared__ u64 sAl[L_SZ];
    __shared__ u64 sSc[L_SZ];
    __shared__ u64 sSh[L_SZ];

    const int k   = blockIdx.y;
    const int tid = threadIdx.x;

    {
        const float* p = W1 + k * L_SZ * 8;
        for (int i = tid; i < L_SZ * 8; i += NTHREADS) ((u64*)sW1)[i] = dup2(p[i]);
        p = b1 + k * L_SZ * 8;
        for (int i = tid; i < L_SZ * 8; i += NTHREADS) ((u64*)sB1)[i] = dup2(p[i]);
        p = W2 + k * L_SZ * 64;
        for (int i = tid; i < L_SZ * 64; i += NTHREADS) ((u64*)sW2)[i] = dup2(p[i]);
        p = b2 + k * L_SZ * 8;
        for (int i = tid; i < L_SZ * 8; i += NTHREADS) ((u64*)sB2)[i] = dup2(p[i]);
        p = W3 + k * L_SZ * 48;
        for (int i = tid; i < L_SZ * 48; i += NTHREADS) ((u64*)sW3)[i] = dup2(p[i]);
        p = b3 + k * L_SZ * 6;
        for (int i = tid; i < L_SZ * 6; i += NTHREADS) ((u64*)sB3)[i] = dup2(p[i]);
        p = W4 + k * L_SZ * 6;
        for (int i = tid; i < L_SZ * 6; i += NTHREADS) ((u64*)sW4)[i] = dup2(p[i]);
        for (int i = tid; i < L_SZ; i += NTHREADS) {
            sB4[i] = dup2(b4[k * L_SZ + i]);
            sAl[i] = dup2(alpha[i * K_SZ + k]);
            sSc[i] = dup2(g_scale[i]);
            sSh[i] = dup2(g_shift[i]);
        }
    }
    __syncthreads();

    const int b0  = blockIdx.x * (2 * NTHREADS) + tid;
    const int b1i = b0 + NTHREADS;
    const float* xr0 = x + b0  * L_SZ;
    const float* xr1 = x + b1i * L_SZ;

    u64 acc = 0ULL;  // {0.f, 0.f}

    #pragma unroll 1
    for (int l = 0; l < L_SZ; ++l) {
        u64 x2 = pack2(xr0[l], xr1[l]);
        u64 xn = ffma2(x2, sSc[l], sSh[l]);

        // layer 1: 1 -> 8
        u64 h1v[8];
        {
            const ulonglong2* w  = (const ulonglong2*)sW1[l];
            const ulonglong2* bb = (const ulonglong2*)sB1[l];
            #pragma unroll
            for (int t = 0; t < 4; ++t) {
                ulonglong2 wv = w[t], bv = bb[t];
                h1v[2*t]   = relu2(ffma2(xn, wv.x, bv.x));
                h1v[2*t+1] = relu2(ffma2(xn, wv.y, bv.y));
            }
        }

        // layer 2: 8 -> 8
        u64 h2v[8];
        #pragma unroll
        for (int i = 0; i < 8; ++i) {
            const ulonglong2* w = (const ulonglong2*)sW2[l][i];
            u64 a = sB2[l][i];
            ulonglong2 w0 = w[0], w1 = w[1], w2 = w[2], w3 = w[3];
            a = ffma2(h1v[0], w0.x, a); a = ffma2(h1v[1], w0.y, a);
            a = ffma2(h1v[2], w1.x, a); a = ffma2(h1v[3], w1.y, a);
            a = ffma2(h1v[4], w2.x, a); a = ffma2(h1v[5], w2.y, a);
            a = ffma2(h1v[6], w3.x, a); a = ffma2(h1v[7], w3.y, a);
            h2v[i] = relu2(a);
        }

        // layer 3: 8 -> 6
        u64 h3v[6];
        #pragma unroll
        for (int j = 0; j < 6; ++j) {
            const ulonglong2* w = (const ulonglong2*)sW3[l][j];
            u64 a = sB3[l][j];
            ulonglong2 w0 = w[0], w1 = w[1], w2 = w[2], w3 = w[3];
            a = ffma2(h2v[0], w0.x, a); a = ffma2(h2v[1], w0.y, a);
            a = ffma2(h2v[2], w1.x, a); a = ffma2(h2v[3], w1.y, a);
            a = ffma2(h2v[4], w2.x, a); a = ffma2(h2v[5], w2.y, a);
            a = ffma2(h2v[6], w3.x, a); a = ffma2(h2v[7], w3.y, a);
            h3v[j] = relu2(a);
        }

        // layer 4: 6 -> 1, then alpha-weighted accumulate
        u64 f = sB4[l];
        #pragma unroll
        for (int j = 0; j < 6; ++j) f = ffma2(h3v[j], sW4[l][j], f);
        acc = ffma2(f, sAl[l], acc);
    }

    float2 r  = unpack2(acc);
    float  bt = beta[k];
    out[b0  * K_SZ + k] = r.x + bt;
    out[b1i * K_SZ + k] = r.y + bt;
}

extern "C" void kernel_launch(void* const* d_in, const int* in_sizes, int n_in,
                              void* d_out, int out_size) {
    const float* x      = (const float*)d_in[0];
    const float* gamma  = (const float*)d_in[1];
    const float* bnb    = (const float*)d_in[2];
    const float* W1     = (const float*)d_in[3];
    const float* b1     = (const float*)d_in[4];
    const float* W2     = (const float*)d_in[5];
    const float* b2     = (const float*)d_in[6];
    const float* W3     = (const float*)d_in[7];
    const float* b3     = (const float*)d_in[8];
    const float* W4     = (const float*)d_in[9];
    const float* b4     = (const float*)d_in[10];
    const float* alpha  = (const float*)d_in[11];
    const float* beta   = (const float*)d_in[12];
    float* out = (float*)d_out;

    bn_stats_kernel<<<L_SZ, 256>>>(x, gamma, bnb);
    mlp_kernel<<<dim3(B_SZ / (2 * NTHREADS), K_SZ), NTHREADS>>>(
        x, W1, b1, W2, b2, W3, b3, W4, b4, alpha, beta, out);
}

// round 2
// speedup vs baseline: 1.3226x; 1.3226x over previous
#include <cuda_runtime.h>

#define B_SZ 8192
#define K_SZ 25
#define L_SZ 25
#define NTHREADS 128
#define ROWS_PT 4                 // batch rows per thread (two f32x2 pairs)
#define BN_EPS 1e-5f

typedef unsigned long long u64;

__device__ float g_scale[L_SZ];
__device__ float g_shift[L_SZ];
__device__ float g_xnT[L_SZ * B_SZ];   // normalized x, transposed [L][B]

// ---------- packed f32x2 helpers ----------
__device__ __forceinline__ u64 pack2(float a, float b) {
    u64 r;
    asm("mov.b64 %0, {%1, %2};" : "=l"(r) : "r"(__float_as_uint(a)), "r"(__float_as_uint(b)));
    return r;
}
__device__ __forceinline__ u64 dup2(float a) { return pack2(a, a); }
__device__ __forceinline__ float2 unpack2(u64 v) {
    unsigned lo, hi;
    asm("mov.b64 {%0, %1}, %2;" : "=r"(lo), "=r"(hi) : "l"(v));
    return make_float2(__uint_as_float(lo), __uint_as_float(hi));
}
__device__ __forceinline__ u64 ffma2(u64 a, u64 b, u64 c) {
    u64 d;
    asm("fma.rn.f32x2 %0, %1, %2, %3;" : "=l"(d) : "l"(a), "l"(b), "l"(c));
    return d;
}
__device__ __forceinline__ u64 add2(u64 a, u64 b) {
    u64 d;
    asm("add.rn.f32x2 %0, %1, %2;" : "=l"(d) : "l"(a), "l"(b));
    return d;
}
__device__ __forceinline__ u64 relu2(u64 v) {
    float2 f = unpack2(v);
    return pack2(fmaxf(f.x, 0.f), fmaxf(f.y, 0.f));
}

// ---------- kernel 1: BatchNorm statistics per column ----------
__global__ void bn_stats_kernel(const float* __restrict__ x,
                                const float* __restrict__ gamma,
                                const float* __restrict__ bn_bias) {
    const int l = blockIdx.x;
    const int tid = threadIdx.x;
    float s = 0.f, q = 0.f;
    for (int b = tid; b < B_SZ; b += 256) {
        float v = x[b * L_SZ + l];
        s += v;
        q = fmaf(v, v, q);
    }
    #pragma unroll
    for (int o = 16; o > 0; o >>= 1) {
        s += __shfl_down_sync(0xFFFFFFFFu, s, o);
        q += __shfl_down_sync(0xFFFFFFFFu, q, o);
    }
    __shared__ float ss[8], sq[8];
    const int w = tid >> 5, ln = tid & 31;
    if (ln == 0) { ss[w] = s; sq[w] = q; }
    __syncthreads();
    if (tid == 0) {
        float S = 0.f, Q = 0.f;
        #pragma unroll
        for (int i = 0; i < 8; ++i) { S += ss[i]; Q += sq[i]; }
        float mean = S / (float)B_SZ;
        float var  = Q / (float)B_SZ - mean * mean;
        float rstd = rsqrtf(var + BN_EPS);
        float sc = gamma[l] * rstd;
        g_scale[l] = sc;
        g_shift[l] = bn_bias[l] - mean * sc;
    }
}

// ---------- kernel 2: normalize + transpose into g_xnT[L][B] ----------
__global__ void __launch_bounds__(256) norm_transpose_kernel(const float* __restrict__ x) {
    __shared__ float t[256][27];           // 27 pad: odd stride, conflict-free column read
    __shared__ float sc[L_SZ], sh[L_SZ];
    const int tid = threadIdx.x;
    const int base = blockIdx.x * 256;
    if (tid < L_SZ) { sc[tid] = g_scale[tid]; sh[tid] = g_shift[tid]; }
    __syncthreads();
    #pragma unroll
    for (int i = tid; i < 256 * L_SZ; i += 256) {
        int r = i / L_SZ, c = i - r * L_SZ;
        t[r][c] = fmaf(x[base * L_SZ + i], sc[c], sh[c]);
    }
    __syncthreads();
    #pragma unroll 1
    for (int l = 0; l < L_SZ; ++l)
        g_xnT[l * B_SZ + base + tid] = t[tid][l];
}

// ---------- kernel 3: fused tiny-MLP ensemble ----------
__global__ void __launch_bounds__(NTHREADS) mlp_kernel(
    const float* __restrict__ W1, const float* __restrict__ b1,
    const float* __restrict__ W2, const float* __restrict__ b2,
    const float* __restrict__ W3, const float* __restrict__ b3,
    const float* __restrict__ W4, const float* __restrict__ b4,
    const float* __restrict__ alpha, const float* __restrict__ beta,
    float* __restrict__ out)
{
    // weights duplicated as {w,w} pairs so each LDS.64/128 feeds FFMA2 directly
    __shared__ __align__(16) u64 sW1[L_SZ][8];
    __shared__ __align__(16) u64 sB1[L_SZ][8];
    __shared__ __align__(16) u64 sW2[L_SZ][8][8];
    __shared__ __align__(16) u64 sB2[L_SZ][8];
    __shared__ __align__(16) u64 sW3[L_SZ][6][8];
    __shared__ u64 sB3[L_SZ][6];
    __shared__ __align__(16) u64 sW4[L_SZ][6];   // pre-scaled by alpha[l,k]
    __shared__ u64 sB4[L_SZ];                    // pre-scaled by alpha[l,k]

    const int k   = blockIdx.y;
    const int tid = threadIdx.x;

    {
        const float* p = W1 + k * L_SZ * 8;
        for (int i = tid; i < L_SZ * 8; i += NTHREADS) ((u64*)sW1)[i] = dup2(p[i]);
        p = b1 + k * L_SZ * 8;
        for (int i = tid; i < L_SZ * 8; i += NTHREADS) ((u64*)sB1)[i] = dup2(p[i]);
        p = W2 + k * L_SZ * 64;
        for (int i = tid; i < L_SZ * 64; i += NTHREADS) ((u64*)sW2)[i] = dup2(p[i]);
        p = b2 + k * L_SZ * 8;
        for (int i = tid; i < L_SZ * 8; i += NTHREADS) ((u64*)sB2)[i] = dup2(p[i]);
        p = W3 + k * L_SZ * 48;
        for (int i = tid; i < L_SZ * 48; i += NTHREADS) ((u64*)sW3)[i] = dup2(p[i]);
        p = b3 + k * L_SZ * 6;
        for (int i = tid; i < L_SZ * 6; i += NTHREADS) ((u64*)sB3)[i] = dup2(p[i]);
        p = W4 + k * L_SZ * 6;
        for (int i = tid; i < L_SZ * 6; i += NTHREADS) {
            int l = i / 6;
            ((u64*)sW4)[i] = dup2(p[i] * alpha[l * K_SZ + k]);
        }
        for (int i = tid; i < L_SZ; i += NTHREADS)
            sB4[i] = dup2(b4[k * L_SZ + i] * alpha[i * K_SZ + k]);
    }
    __syncthreads();

    const int b0 = (blockIdx.x * NTHREADS + tid) * ROWS_PT;
    const float bt = beta[k];
    u64 accA = dup2(bt);
    u64 accB = dup2(bt);

    #pragma unroll 1
    for (int l = 0; l < L_SZ; ++l) {
        float4 xv = *(const float4*)(g_xnT + l * B_SZ + b0);   // 4 consecutive rows, coalesced
        u64 xnA = pack2(xv.x, xv.y);
        u64 xnB = pack2(xv.z, xv.w);

        // layer 1: 1 -> 8  (weights shared across both pairs)
        u64 h1A[8], h1B[8];
        {
            const ulonglong2* w  = (const ulonglong2*)sW1[l];
            const ulonglong2* bb = (const ulonglong2*)sB1[l];
            #pragma unroll
            for (int t = 0; t < 4; ++t) {
                ulonglong2 wv = w[t], bv = bb[t];
                h1A[2*t]   = relu2(ffma2(xnA, wv.x, bv.x));
                h1B[2*t]   = relu2(ffma2(xnB, wv.x, bv.x));
                h1A[2*t+1] = relu2(ffma2(xnA, wv.y, bv.y));
                h1B[2*t+1] = relu2(ffma2(xnB, wv.y, bv.y));
            }
        }

        // layer 2: 8 -> 8
        u64 h2A[8], h2B[8];
        #pragma unroll
        for (int i = 0; i < 8; ++i) {
            const ulonglong2* w = (const ulonglong2*)sW2[l][i];
            ulonglong2 w0 = w[0], w1 = w[1], w2 = w[2], w3 = w[3];
            u64 bi = sB2[l][i];
            u64 a = bi, b = bi;
            a = ffma2(h1A[0], w0.x, a); b = ffma2(h1B[0], w0.x, b);
            a = ffma2(h1A[1], w0.y, a); b = ffma2(h1B[1], w0.y, b);
            a = ffma2(h1A[2], w1.x, a); b = ffma2(h1B[2], w1.x, b);
            a = ffma2(h1A[3], w1.y, a); b = ffma2(h1B[3], w1.y, b);
            a = ffma2(h1A[4], w2.x, a); b = ffma2(h1B[4], w2.x, b);
            a = ffma2(h1A[5], w2.y, a); b = ffma2(h1B[5], w2.y, b);
            a = ffma2(h1A[6], w3.x, a); b = ffma2(h1B[6], w3.x, b);
            a = ffma2(h1A[7], w3.y, a); b = ffma2(h1B[7], w3.y, b);
            h2A[i] = relu2(a);
            h2B[i] = relu2(b);
        }

        // layer 3: 8 -> 6
        u64 h3A[6], h3B[6];
        #pragma unroll
        for (int j = 0; j < 6; ++j) {
            const ulonglong2* w = (const ulonglong2*)sW3[l][j];
            ulonglong2 w0 = w[0], w1 = w[1], w2 = w[2], w3 = w[3];
            u64 bj = sB3[l][j];
            u64 a = bj, b = bj;
            a = ffma2(h2A[0], w0.x, a); b = ffma2(h2B[0], w0.x, b);
            a = ffma2(h2A[1], w0.y, a); b = ffma2(h2B[1], w0.y, b);
            a = ffma2(h2A[2], w1.x, a); b = ffma2(h2B[2], w1.x, b);
            a = ffma2(h2A[3], w1.y, a); b = ffma2(h2B[3], w1.y, b);
            a = ffma2(h2A[4], w2.x, a); b = ffma2(h2B[4], w2.x, b);
            a = ffma2(h2A[5], w2.y, a); b = ffma2(h2B[5], w2.y, b);
            a = ffma2(h2A[6], w3.x, a); b = ffma2(h2B[6], w3.x, b);
            a = ffma2(h2A[7], w3.y, a); b = ffma2(h2B[7], w3.y, b);
            h3A[j] = relu2(a);
            h3B[j] = relu2(b);
        }

        // layer 4 (alpha pre-folded): f = sB4 + sum_j h3*sW4; acc += f
        u64 fA = sB4[l], fB = sB4[l];
        {
            const ulonglong2* w = (const ulonglong2*)sW4[l];
            ulonglong2 w0 = w[0], w1 = w[1], w2 = w[2];
            fA = ffma2(h3A[0], w0.x, fA); fB = ffma2(h3B[0], w0.x, fB);
            fA = ffma2(h3A[1], w0.y, fA); fB = ffma2(h3B[1], w0.y, fB);
            fA = ffma2(h3A[2], w1.x, fA); fB = ffma2(h3B[2], w1.x, fB);
            fA = ffma2(h3A[3], w1.y, fA); fB = ffma2(h3B[3], w1.y, fB);
            fA = ffma2(h3A[4], w2.x, fA); fB = ffma2(h3B[4], w2.x, fB);
            fA = ffma2(h3A[5], w2.y, fA); fB = ffma2(h3B[5], w2.y, fB);
        }
        accA = add2(accA, fA);
        accB = add2(accB, fB);
    }

    float2 rA = unpack2(accA);
    float2 rB = unpack2(accB);
    out[(b0 + 0) * K_SZ + k] = rA.x;
    out[(b0 + 1) * K_SZ + k] = rA.y;
    out[(b0 + 2) * K_SZ + k] = rB.x;
    out[(b0 + 3) * K_SZ + k] = rB.y;
}

extern "C" void kernel_launch(void* const* d_in, const int* in_sizes, int n_in,
                              void* d_out, int out_size) {
    const float* x      = (const float*)d_in[0];
    const float* gamma  = (const float*)d_in[1];
    const float* bnb    = (const float*)d_in[2];
    const float* W1     = (const float*)d_in[3];
    const float* b1     = (const float*)d_in[4];
    const float* W2     = (const float*)d_in[5];
    const float* b2     = (const float*)d_in[6];
    const float* W3     = (const float*)d_in[7];
    const float* b3     = (const float*)d_in[8];
    const float* W4     = (const float*)d_in[9];
    const float* b4     = (const float*)d_in[10];
    const float* alpha  = (const float*)d_in[11];
    const float* beta   = (const float*)d_in[12];
    float* out = (float*)d_out;

    bn_stats_kernel<<<L_SZ, 256>>>(x, gamma, bnb);
    norm_transpose_kernel<<<B_SZ / 256, 256>>>(x);
    mlp_kernel<<<dim3(B_SZ / (ROWS_PT * NTHREADS), K_SZ), NTHREADS>>>(
        W1, b1, W2, b2, W3, b3, W4, b4, alpha, beta, out);
}

// round 3
// speedup vs baseline: 1.4491x; 1.0957x over previous
#include <cuda_runtime.h>

#define B_SZ 8192
#define K_SZ 25
#define L_SZ 25
#define NTHREADS 128
#define ROWS_PT 4                 // batch rows per thread (two f32x2 pairs)
#define LSPLIT 2                  // l-range split across blocks
#define BN_EPS 1e-5f

typedef unsigned long long u64;

__device__ float g_sum[L_SZ];
__device__ float g_sumsq[L_SZ];
__device__ float g_xnT[L_SZ * B_SZ];   // normalized x, transposed [L][B]

// ---------- packed f32x2 helpers ----------
__device__ __forceinline__ u64 pack2(float a, float b) {
    u64 r;
    asm("mov.b64 %0, {%1, %2};" : "=l"(r) : "r"(__float_as_uint(a)), "r"(__float_as_uint(b)));
    return r;
}
__device__ __forceinline__ u64 dup2(float a) { return pack2(a, a); }
__device__ __forceinline__ float2 unpack2(u64 v) {
    unsigned lo, hi;
    asm("mov.b64 {%0, %1}, %2;" : "=r"(lo), "=r"(hi) : "l"(v));
    return make_float2(__uint_as_float(lo), __uint_as_float(hi));
}
__device__ __forceinline__ u64 ffma2(u64 a, u64 b, u64 c) {
    u64 d;
    asm("fma.rn.f32x2 %0, %1, %2, %3;" : "=l"(d) : "l"(a), "l"(b), "l"(c));
    return d;
}
__device__ __forceinline__ u64 add2(u64 a, u64 b) {
    u64 d;
    asm("add.rn.f32x2 %0, %1, %2;" : "=l"(d) : "l"(a), "l"(b));
    return d;
}
__device__ __forceinline__ u64 relu2(u64 v) {
    float2 f = unpack2(v);
    return pack2(fmaxf(f.x, 0.f), fmaxf(f.y, 0.f));
}

// ---------- kernel 1: BN partial sums, 200 blocks ----------
__global__ void __launch_bounds__(256) bn_stats_kernel(const float* __restrict__ x) {
    const int l   = blockIdx.x;
    const int tid = threadIdx.x;
    const int r0  = blockIdx.y * (B_SZ / 8);
    float s = 0.f, q = 0.f;
    #pragma unroll
    for (int i = 0; i < (B_SZ / 8) / 256; ++i) {
        float v = x[(r0 + i * 256 + tid) * L_SZ + l];
        s += v;
        q = fmaf(v, v, q);
    }
    #pragma unroll
    for (int o = 16; o > 0; o >>= 1) {
        s += __shfl_down_sync(0xFFFFFFFFu, s, o);
        q += __shfl_down_sync(0xFFFFFFFFu, q, o);
    }
    __shared__ float ss[8], sq[8];
    const int w = tid >> 5, ln = tid & 31;
    if (ln == 0) { ss[w] = s; sq[w] = q; }
    __syncthreads();
    if (tid == 0) {
        float S = 0.f, Q = 0.f;
        #pragma unroll
        for (int i = 0; i < 8; ++i) { S += ss[i]; Q += sq[i]; }
        atomicAdd(&g_sum[l], S);
        atomicAdd(&g_sumsq[l], Q);
    }
}

// ---------- kernel 2: finalize stats + normalize + transpose + init out ----------
__global__ void __launch_bounds__(128) norm_transpose_kernel(
    const float* __restrict__ x,
    const float* __restrict__ gamma, const float* __restrict__ bn_bias,
    const float* __restrict__ beta, float* __restrict__ out)
{
    __shared__ float t[128][27];          // odd stride: conflict-free column read
    __shared__ float sc[L_SZ], sh[L_SZ], sbeta[L_SZ];
    const int tid  = threadIdx.x;
    const int base = blockIdx.x * 128;
    if (tid < L_SZ) {
        float mean = g_sum[tid] * (1.f / (float)B_SZ);
        float var  = g_sumsq[tid] * (1.f / (float)B_SZ) - mean * mean;
        float s    = gamma[tid] * rsqrtf(var + BN_EPS);
        sc[tid] = s;
        sh[tid] = bn_bias[tid] - mean * s;
        sbeta[tid] = beta[tid];
    }
    __syncthreads();
    #pragma unroll
    for (int i = tid; i < 128 * L_SZ; i += 128) {
        int r = i / L_SZ, c = i - r * L_SZ;
        t[r][c] = fmaf(x[base * L_SZ + i], sc[c], sh[c]);
        out[base * L_SZ + i] = sbeta[c];      // init out with beta[k]
    }
    __syncthreads();
    #pragma unroll 1
    for (int l = 0; l < L_SZ; ++l)
        g_xnT[l * B_SZ + base + tid] = t[tid][l];
}

// ---------- kernel 3: fused tiny-MLP ensemble, l-split, atomic combine ----------
__global__ void __launch_bounds__(NTHREADS) mlp_kernel(
    const float* __restrict__ W1, const float* __restrict__ b1,
    const float* __restrict__ W2, const float* __restrict__ b2,
    const float* __restrict__ W3, const float* __restrict__ b3,
    const float* __restrict__ W4, const float* __restrict__ b4,
    const float* __restrict__ alpha,
    float* __restrict__ out)
{
    __shared__ __align__(16) u64 sW1[L_SZ][8];
    __shared__ __align__(16) u64 sB1[L_SZ][8];
    __shared__ __align__(16) u64 sW2[L_SZ][8][8];
    __shared__ __align__(16) u64 sB2[L_SZ][8];
    __shared__ __align__(16) u64 sW3[L_SZ][6][8];
    __shared__ u64 sB3[L_SZ][6];
    __shared__ __align__(16) u64 sW4[L_SZ][6];   // pre-scaled by alpha[l,k]
    __shared__ u64 sB4[L_SZ];                    // pre-scaled by alpha[l,k]

    const int k      = blockIdx.y;
    const int tid    = threadIdx.x;
    const int lstart = blockIdx.z ? 13 : 0;
    const int lend   = blockIdx.z ? 25 : 13;

    {
        const float* p = W1 + k * L_SZ * 8;
        for (int i = lstart * 8 + tid; i < lend * 8; i += NTHREADS) ((u64*)sW1)[i] = dup2(p[i]);
        p = b1 + k * L_SZ * 8;
        for (int i = lstart * 8 + tid; i < lend * 8; i += NTHREADS) ((u64*)sB1)[i] = dup2(p[i]);
        p = W2 + k * L_SZ * 64;
        for (int i = lstart * 64 + tid; i < lend * 64; i += NTHREADS) ((u64*)sW2)[i] = dup2(p[i]);
        p = b2 + k * L_SZ * 8;
        for (int i = lstart * 8 + tid; i < lend * 8; i += NTHREADS) ((u64*)sB2)[i] = dup2(p[i]);
        p = W3 + k * L_SZ * 48;
        for (int i = lstart * 48 + tid; i < lend * 48; i += NTHREADS) ((u64*)sW3)[i] = dup2(p[i]);
        p = b3 + k * L_SZ * 6;
        for (int i = lstart * 6 + tid; i < lend * 6; i += NTHREADS) ((u64*)sB3)[i] = dup2(p[i]);
        p = W4 + k * L_SZ * 6;
        for (int i = lstart * 6 + tid; i < lend * 6; i += NTHREADS) {
            int l = i / 6;
            ((u64*)sW4)[i] = dup2(p[i] * alpha[l * K_SZ + k]);
        }
        for (int i = lstart + tid; i < lend; i += NTHREADS)
            sB4[i] = dup2(b4[k * L_SZ + i] * alpha[i * K_SZ + k]);
    }
    __syncthreads();

    const int b0 = (blockIdx.x * NTHREADS + tid) * ROWS_PT;
    u64 accA = 0ULL, accB = 0ULL;

    // software-pipelined x load
    float4 xv = *(const float4*)(g_xnT + lstart * B_SZ + b0);

    #pragma unroll 1
    for (int l = lstart; l < lend; ++l) {
        float4 xnext;
        if (l + 1 < lend) xnext = *(const float4*)(g_xnT + (l + 1) * B_SZ + b0);
        u64 xnA = pack2(xv.x, xv.y);
        u64 xnB = pack2(xv.z, xv.w);

        // layer 1: 1 -> 8
        u64 h1A[8], h1B[8];
        {
            const ulonglong2* w  = (const ulonglong2*)sW1[l];
            const ulonglong2* bb = (const ulonglong2*)sB1[l];
            #pragma unroll
            for (int t = 0; t < 4; ++t) {
                ulonglong2 wv = w[t], bv = bb[t];
                h1A[2*t]   = relu2(ffma2(xnA, wv.x, bv.x));
                h1B[2*t]   = relu2(ffma2(xnB, wv.x, bv.x));
                h1A[2*t+1] = relu2(ffma2(xnA, wv.y, bv.y));
                h1B[2*t+1] = relu2(ffma2(xnB, wv.y, bv.y));
            }
        }

        // layer 2: 8 -> 8
        u64 h2A[8], h2B[8];
        #pragma unroll
        for (int i = 0; i < 8; ++i) {
            const ulonglong2* w = (const ulonglong2*)sW2[l][i];
            ulonglong2 w0 = w[0], w1 = w[1], w2 = w[2], w3 = w[3];
            u64 bi = sB2[l][i];
            u64 a = bi, b = bi;
            a = ffma2(h1A[0], w0.x, a); b = ffma2(h1B[0], w0.x, b);
            a = ffma2(h1A[1], w0.y, a); b = ffma2(h1B[1], w0.y, b);
            a = ffma2(h1A[2], w1.x, a); b = ffma2(h1B[2], w1.x, b);
            a = ffma2(h1A[3], w1.y, a); b = ffma2(h1B[3], w1.y, b);
            a = ffma2(h1A[4], w2.x, a); b = ffma2(h1B[4], w2.x, b);
            a = ffma2(h1A[5], w2.y, a); b = ffma2(h1B[5], w2.y, b);
            a = ffma2(h1A[6], w3.x, a); b = ffma2(h1B[6], w3.x, b);
            a = ffma2(h1A[7], w3.y, a); b = ffma2(h1B[7], w3.y, b);
            h2A[i] = relu2(a);
            h2B[i] = relu2(b);
        }

        // layer 3: 8 -> 6
        u64 h3A[6], h3B[6];
        #pragma unroll
        for (int j = 0; j < 6; ++j) {
            const ulonglong2* w = (const ulonglong2*)sW3[l][j];
            ulonglong2 w0 = w[0], w1 = w[1], w2 = w[2], w3 = w[3];
            u64 bj = sB3[l][j];
            u64 a = bj, b = bj;
            a = ffma2(h2A[0], w0.x, a); b = ffma2(h2B[0], w0.x, b);
            a = ffma2(h2A[1], w0.y, a); b = ffma2(h2B[1], w0.y, b);
            a = ffma2(h2A[2], w1.x, a); b = ffma2(h2B[2], w1.x, b);
            a = ffma2(h2A[3], w1.y, a); b = ffma2(h2B[3], w1.y, b);
            a = ffma2(h2A[4], w2.x, a); b = ffma2(h2B[4], w2.x, b);
            a = ffma2(h2A[5], w2.y, a); b = ffma2(h2B[5], w2.y, b);
            a = ffma2(h2A[6], w3.x, a); b = ffma2(h2B[6], w3.x, b);
            a = ffma2(h2A[7], w3.y, a); b = ffma2(h2B[7], w3.y, b);
            h3A[j] = relu2(a);
            h3B[j] = relu2(b);
        }

        // layer 4 (alpha pre-folded)
        u64 fA = sB4[l], fB = sB4[l];
        {
            const ulonglong2* w = (const ulonglong2*)sW4[l];
            ulonglong2 w0 = w[0], w1 = w[1], w2 = w[2];
            fA = ffma2(h3A[0], w0.x, fA); fB = ffma2(h3B[0], w0.x, fB);
            fA = ffma2(h3A[1], w0.y, fA); fB = ffma2(h3B[1], w0.y, fB);
            fA = ffma2(h3A[2], w1.x, fA); fB = ffma2(h3B[2], w1.x, fB);
            fA = ffma2(h3A[3], w1.y, fA); fB = ffma2(h3B[3], w1.y, fB);
            fA = ffma2(h3A[4], w2.x, fA); fB = ffma2(h3B[4], w2.x, fB);
            fA = ffma2(h3A[5], w2.y, fA); fB = ffma2(h3B[5], w2.y, fB);
        }
        accA = add2(accA, fA);
        accB = add2(accB, fB);
        xv = xnext;
    }

    float2 rA = unpack2(accA);
    float2 rB = unpack2(accB);
    atomicAdd(out + (b0 + 0) * K_SZ + k, rA.x);
    atomicAdd(out + (b0 + 1) * K_SZ + k, rA.y);
    atomicAdd(out + (b0 + 2) * K_SZ + k, rB.x);
    atomicAdd(out + (b0 + 3) * K_SZ + k, rB.y);
}

extern "C" void kernel_launch(void* const* d_in, const int* in_sizes, int n_in,
                              void* d_out, int out_size) {
    const float* x      = (const float*)d_in[0];
    const float* gamma  = (const float*)d_in[1];
    const float* bnb    = (const float*)d_in[2];
    const float* W1     = (const float*)d_in[3];
    const float* b1     = (const float*)d_in[4];
    const float* W2     = (const float*)d_in[5];
    const float* b2     = (const float*)d_in[6];
    const float* W3     = (const float*)d_in[7];
    const float* b3     = (const float*)d_in[8];
    const float* W4     = (const float*)d_in[9];
    const float* b4     = (const float*)d_in[10];
    const float* alpha  = (const float*)d_in[11];
    const float* beta   = (const float*)d_in[12];
    float* out = (float*)d_out;

    void* p_sum = nullptr;
    void* p_sq  = nullptr;
    cudaGetSymbolAddress(&p_sum, g_sum);
    cudaGetSymbolAddress(&p_sq,  g_sumsq);
    cudaMemsetAsync(p_sum, 0, L_SZ * sizeof(float));
    cudaMemsetAsync(p_sq,  0, L_SZ * sizeof(float));

    bn_stats_kernel<<<dim3(L_SZ, 8), 256>>>(x);
    norm_transpose_kernel<<<B_SZ / 128, 128>>>(x, gamma, bnb, beta, out);
    mlp_kernel<<<dim3(B_SZ / (ROWS_PT * NTHREADS), K_SZ, LSPLIT), NTHREADS>>>(
        W1, b1, W2, b2, W3, b3, W4, b4, alpha, out);
}

// round 4
// speedup vs baseline: 1.5095x; 1.0417x over previous
#include <cuda_runtime.h>

#define B_SZ 8192
#define K_SZ 25
#define L_SZ 25
#define NTHREADS 128
#define ROWS_PT 4                 // batch rows per thread (two f32x2 pairs)
#define LSPLIT 2                  // l-range split across blocks
#define BN_EPS 1e-5f

typedef unsigned long long u64;

__device__ float g_sum[L_SZ];
__device__ float g_sumsq[L_SZ];
__device__ float g_xT[L_SZ * B_SZ];   // raw x, transposed [L][B]

// ---------- packed f32x2 helpers ----------
__device__ __forceinline__ u64 pack2(float a, float b) {
    u64 r;
    asm("mov.b64 %0, {%1, %2};" : "=l"(r) : "r"(__float_as_uint(a)), "r"(__float_as_uint(b)));
    return r;
}
__device__ __forceinline__ u64 dup2(float a) { return pack2(a, a); }
__device__ __forceinline__ float2 unpack2(u64 v) {
    unsigned lo, hi;
    asm("mov.b64 {%0, %1}, %2;" : "=r"(lo), "=r"(hi) : "l"(v));
    return make_float2(__uint_as_float(lo), __uint_as_float(hi));
}
__device__ __forceinline__ u64 ffma2(u64 a, u64 b, u64 c) {
    u64 d;
    asm("fma.rn.f32x2 %0, %1, %2, %3;" : "=l"(d) : "l"(a), "l"(b), "l"(c));
    return d;
}
__device__ __forceinline__ u64 add2(u64 a, u64 b) {
    u64 d;
    asm("add.rn.f32x2 %0, %1, %2;" : "=l"(d) : "l"(a), "l"(b));
    return d;
}
__device__ __forceinline__ u64 relu2(u64 v) {
    float2 f = unpack2(v);
    return pack2(fmaxf(f.x, 0.f), fmaxf(f.y, 0.f));
}

// ---------- kernel 1: fused stats + transpose + out-init (all coalesced) ----------
__global__ void __launch_bounds__(128) prologue_kernel(
    const float* __restrict__ x,
    const float* __restrict__ beta,
    float* __restrict__ out)
{
    __shared__ float t[128][27];          // odd pad: conflict-free column access
    __shared__ float ps[4][32], pq[4][32];
    __shared__ float sbeta[L_SZ];
    const int tid  = threadIdx.x;
    const int base = blockIdx.x * 128;

    if (tid < L_SZ) sbeta[tid] = beta[tid];
    __syncthreads();

    // coalesced load of 128 rows x 25 cols; also init out with beta[k]
    #pragma unroll
    for (int i = tid; i < 128 * L_SZ; i += 128) {
        int r = i / L_SZ, c = i - r * L_SZ;
        float v = x[base * L_SZ + i];
        t[r][c] = v;
        out[base * L_SZ + i] = sbeta[c];
    }
    __syncthreads();

    // per-column partial sums: thread group g=tid/32 handles rows g::4
    {
        const int c = tid & 31, g = tid >> 5;
        float s = 0.f, q = 0.f;
        if (c < L_SZ) {
            #pragma unroll
            for (int r = g; r < 128; r += 4) {
                float v = t[r][c];
                s += v;
                q = fmaf(v, v, q);
            }
        }
        ps[g][c] = s;
        pq[g][c] = q;
    }
    __syncthreads();
    if (tid < L_SZ) {
        float S = ps[0][tid] + ps[1][tid] + ps[2][tid] + ps[3][tid];
        float Q = pq[0][tid] + pq[1][tid] + pq[2][tid] + pq[3][tid];
        atomicAdd(&g_sum[tid], S);
        atomicAdd(&g_sumsq[tid], Q);
    }

    // transpose write (coalesced, 128-wide)
    #pragma unroll 1
    for (int l = 0; l < L_SZ; ++l)
        g_xT[l * B_SZ + base + tid] = t[tid][l];
}

// ---------- kernel 2: fused tiny-MLP ensemble (BN applied in-loop) ----------
__global__ void __launch_bounds__(NTHREADS) mlp_kernel(
    const float* __restrict__ gamma, const float* __restrict__ bn_bias,
    const float* __restrict__ W1, const float* __restrict__ b1,
    const float* __restrict__ W2, const float* __restrict__ b2,
    const float* __restrict__ W3, const float* __restrict__ b3,
    const float* __restrict__ W4, const float* __restrict__ b4,
    const float* __restrict__ alpha,
    float* __restrict__ out)
{
    __shared__ __align__(16) u64 sW1[L_SZ][8];
    __shared__ __align__(16) u64 sB1[L_SZ][8];
    __shared__ __align__(16) u64 sW2[L_SZ][8][8];
    __shared__ __align__(16) u64 sB2[L_SZ][8];
    __shared__ __align__(16) u64 sW3[L_SZ][6][8];
    __shared__ u64 sB3[L_SZ][6];
    __shared__ __align__(16) u64 sW4[L_SZ][6];   // pre-scaled by alpha[l,k]
    __shared__ u64 sB4[L_SZ];                    // pre-scaled by alpha[l,k]
    __shared__ u64 sSc[L_SZ], sSh[L_SZ];         // BN scale/shift (dup2)

    const int k      = blockIdx.y;
    const int tid    = threadIdx.x;
    const int lstart = blockIdx.z ? 13 : 0;
    const int lend   = blockIdx.z ? 25 : 13;

    {
        const float* p = W1 + k * L_SZ * 8;
        for (int i = lstart * 8 + tid; i < lend * 8; i += NTHREADS) ((u64*)sW1)[i] = dup2(p[i]);
        p = b1 + k * L_SZ * 8;
        for (int i = lstart * 8 + tid; i < lend * 8; i += NTHREADS) ((u64*)sB1)[i] = dup2(p[i]);
        p = W2 + k * L_SZ * 64;
        for (int i = lstart * 64 + tid; i < lend * 64; i += NTHREADS) ((u64*)sW2)[i] = dup2(p[i]);
        p = b2 + k * L_SZ * 8;
        for (int i = lstart * 8 + tid; i < lend * 8; i += NTHREADS) ((u64*)sB2)[i] = dup2(p[i]);
        p = W3 + k * L_SZ * 48;
        for (int i = lstart * 48 + tid; i < lend * 48; i += NTHREADS) ((u64*)sW3)[i] = dup2(p[i]);
        p = b3 + k * L_SZ * 6;
        for (int i = lstart * 6 + tid; i < lend * 6; i += NTHREADS) ((u64*)sB3)[i] = dup2(p[i]);
        p = W4 + k * L_SZ * 6;
        for (int i = lstart * 6 + tid; i < lend * 6; i += NTHREADS) {
            int l = i / 6;
            ((u64*)sW4)[i] = dup2(p[i] * alpha[l * K_SZ + k]);
        }
        for (int i = lstart + tid; i < lend; i += NTHREADS) {
            sB4[i] = dup2(b4[k * L_SZ + i] * alpha[i * K_SZ + k]);
            // BN finalize (redundant per block; trivial cost)
            float mean = g_sum[i] * (1.f / (float)B_SZ);
            float var  = g_sumsq[i] * (1.f / (float)B_SZ) - mean * mean;
            float s    = gamma[i] * rsqrtf(var + BN_EPS);
            sSc[i] = dup2(s);
            sSh[i] = dup2(bn_bias[i] - mean * s);
        }
    }
    __syncthreads();

    const int b0 = (blockIdx.x * NTHREADS + tid) * ROWS_PT;
    u64 accA = 0ULL, accB = 0ULL;

    // software-pipelined x load (raw; normalized in-loop)
    float4 xv = *(const float4*)(g_xT + lstart * B_SZ + b0);

    #pragma unroll 1
    for (int l = lstart; l < lend; ++l) {
        float4 xnext;
        if (l + 1 < lend) xnext = *(const float4*)(g_xT + (l + 1) * B_SZ + b0);
        u64 scl = sSc[l], shl = sSh[l];
        u64 xnA = ffma2(pack2(xv.x, xv.y), scl, shl);
        u64 xnB = ffma2(pack2(xv.z, xv.w), scl, shl);

        // layer 1: 1 -> 8
        u64 h1A[8], h1B[8];
        {
            const ulonglong2* w  = (const ulonglong2*)sW1[l];
            const ulonglong2* bb = (const ulonglong2*)sB1[l];
            #pragma unroll
            for (int t = 0; t < 4; ++t) {
                ulonglong2 wv = w[t], bv = bb[t];
                h1A[2*t]   = relu2(ffma2(xnA, wv.x, bv.x));
                h1B[2*t]   = relu2(ffma2(xnB, wv.x, bv.x));
                h1A[2*t+1] = relu2(ffma2(xnA, wv.y, bv.y));
                h1B[2*t+1] = relu2(ffma2(xnB, wv.y, bv.y));
            }
        }

        // layer 2: 8 -> 8
        u64 h2A[8], h2B[8];
        #pragma unroll
        for (int i = 0; i < 8; ++i) {
            const ulonglong2* w = (const ulonglong2*)sW2[l][i];
            ulonglong2 w0 = w[0], w1 = w[1], w2 = w[2], w3 = w[3];
            u64 bi = sB2[l][i];
            u64 a = bi, b = bi;
            a = ffma2(h1A[0], w0.x, a); b = ffma2(h1B[0], w0.x, b);
            a = ffma2(h1A[1], w0.y, a); b = ffma2(h1B[1], w0.y, b);
            a = ffma2(h1A[2], w1.x, a); b = ffma2(h1B[2], w1.x, b);
            a = ffma2(h1A[3], w1.y, a); b = ffma2(h1B[3], w1.y, b);
            a = ffma2(h1A[4], w2.x, a); b = ffma2(h1B[4], w2.x, b);
            a = ffma2(h1A[5], w2.y, a); b = ffma2(h1B[5], w2.y, b);
            a = ffma2(h1A[6], w3.x, a); b = ffma2(h1B[6], w3.x, b);
            a = ffma2(h1A[7], w3.y, a); b = ffma2(h1B[7], w3.y, b);
            h2A[i] = relu2(a);
            h2B[i] = relu2(b);
        }

        // layer 3: 8 -> 6
        u64 h3A[6], h3B[6];
        #pragma unroll
        for (int j = 0; j < 6; ++j) {
            const ulonglong2* w = (const ulonglong2*)sW3[l][j];
            ulonglong2 w0 = w[0], w1 = w[1], w2 = w[2], w3 = w[3];
            u64 bj = sB3[l][j];
            u64 a = bj, b = bj;
            a = ffma2(h2A[0], w0.x, a); b = ffma2(h2B[0], w0.x, b);
            a = ffma2(h2A[1], w0.y, a); b = ffma2(h2B[1], w0.y, b);
            a = ffma2(h2A[2], w1.x, a); b = ffma2(h2B[2], w1.x, b);
            a = ffma2(h2A[3], w1.y, a); b = ffma2(h2B[3], w1.y, b);
            a = ffma2(h2A[4], w2.x, a); b = ffma2(h2B[4], w2.x, b);
            a = ffma2(h2A[5], w2.y, a); b = ffma2(h2B[5], w2.y, b);
            a = ffma2(h2A[6], w3.x, a); b = ffma2(h2B[6], w3.x, b);
            a = ffma2(h2A[7], w3.y, a); b = ffma2(h2B[7], w3.y, b);
            h3A[j] = relu2(a);
            h3B[j] = relu2(b);
        }

        // layer 4 (alpha pre-folded)
        u64 fA = sB4[l], fB = sB4[l];
        {
            const ulonglong2* w = (const ulonglong2*)sW4[l];
            ulonglong2 w0 = w[0], w1 = w[1], w2 = w[2];
            fA = ffma2(h3A[0], w0.x, fA); fB = ffma2(h3B[0], w0.x, fB);
            fA = ffma2(h3A[1], w0.y, fA); fB = ffma2(h3B[1], w0.y, fB);
            fA = ffma2(h3A[2], w1.x, fA); fB = ffma2(h3B[2], w1.x, fB);
            fA = ffma2(h3A[3], w1.y, fA); fB = ffma2(h3B[3], w1.y, fB);
            fA = ffma2(h3A[4], w2.x, fA); fB = ffma2(h3B[4], w2.x, fB);
            fA = ffma2(h3A[5], w2.y, fA); fB = ffma2(h3B[5], w2.y, fB);
        }
        accA = add2(accA, fA);
        accB = add2(accB, fB);
        xv = xnext;
    }

    float2 rA = unpack2(accA);
    float2 rB = unpack2(accB);
    atomicAdd(out + (b0 + 0) * K_SZ + k, rA.x);
    atomicAdd(out + (b0 + 1) * K_SZ + k, rA.y);
    atomicAdd(out + (b0 + 2) * K_SZ + k, rB.x);
    atomicAdd(out + (b0 + 3) * K_SZ + k, rB.y);
}

extern "C" void kernel_launch(void* const* d_in, const int* in_sizes, int n_in,
                              void* d_out, int out_size) {
    const float* x      = (const float*)d_in[0];
    const float* gamma  = (const float*)d_in[1];
    const float* bnb    = (const float*)d_in[2];
    const float* W1     = (const float*)d_in[3];
    const float* b1     = (const float*)d_in[4];
    const float* W2     = (const float*)d_in[5];
    const float* b2     = (const float*)d_in[6];
    const float* W3     = (const float*)d_in[7];
    const float* b3     = (const float*)d_in[8];
    const float* W4     = (const float*)d_in[9];
    const float* b4     = (const float*)d_in[10];
    const float* alpha  = (const float*)d_in[11];
    const float* beta   = (const float*)d_in[12];
    float* out = (float*)d_out;

    void* p_sum = nullptr;
    void* p_sq  = nullptr;
    cudaGetSymbolAddress(&p_sum, g_sum);
    cudaGetSymbolAddress(&p_sq,  g_sumsq);
    cudaMemsetAsync(p_sum, 0, L_SZ * sizeof(float));
    cudaMemsetAsync(p_sq,  0, L_SZ * sizeof(float));

    prologue_kernel<<<B_SZ / 128, 128>>>(x, beta, out);
    mlp_kernel<<<dim3(B_SZ / (ROWS_PT * NTHREADS), K_SZ, LSPLIT), NTHREADS>>>(
        gamma, bnb, W1, b1, W2, b2, W3, b3, W4, b4, alpha, out);
}

// round 5
// speedup vs baseline: 1.6545x; 1.0960x over previous
#include <cuda_runtime.h>

#define B_SZ 8192
#define K_SZ 25
#define L_SZ 25
#define NTHREADS 128
#define ROWS_PT 4                 // batch rows per thread (two f32x2 pairs)
#define LSPLIT 2                  // l-range split across blocks
#define LCHUNK 13                 // max l's per block
#define BN_EPS 1e-5f

typedef unsigned long long u64;

__device__ float g_sum[L_SZ];
__device__ float g_sumsq[L_SZ];
__device__ float g_xT[L_SZ * B_SZ];   // raw x, transposed [L][B]

// ---------- packed f32x2 helpers ----------
__device__ __forceinline__ u64 pack2(float a, float b) {
    u64 r;
    asm("mov.b64 %0, {%1, %2};" : "=l"(r) : "r"(__float_as_uint(a)), "r"(__float_as_uint(b)));
    return r;
}
__device__ __forceinline__ u64 dup2(float a) { return pack2(a, a); }
__device__ __forceinline__ float2 unpack2(u64 v) {
    unsigned lo, hi;
    asm("mov.b64 {%0, %1}, %2;" : "=r"(lo), "=r"(hi) : "l"(v));
    return make_float2(__uint_as_float(lo), __uint_as_float(hi));
}
__device__ __forceinline__ u64 ffma2(u64 a, u64 b, u64 c) {
    u64 d;
    asm("fma.rn.f32x2 %0, %1, %2, %3;" : "=l"(d) : "l"(a), "l"(b), "l"(c));
    return d;
}
__device__ __forceinline__ u64 add2(u64 a, u64 b) {
    u64 d;
    asm("add.rn.f32x2 %0, %1, %2;" : "=l"(d) : "l"(a), "l"(b));
    return d;
}
__device__ __forceinline__ u64 relu2(u64 v) {
    float2 f = unpack2(v);
    return pack2(fmaxf(f.x, 0.f), fmaxf(f.y, 0.f));
}

// ---------- kernel 1: fused stats + transpose + out-init (128 blocks x 64 rows) ----------
__global__ void __launch_bounds__(128) prologue_kernel(
    const float* __restrict__ x,
    const float* __restrict__ beta,
    float* __restrict__ out)
{
    __shared__ float t[64][27];
    __shared__ float ps[4][32], pq[4][32];
    __shared__ float sbeta[L_SZ];
    const int tid  = threadIdx.x;
    const int base = blockIdx.x * 64;

    if (tid < L_SZ) sbeta[tid] = beta[tid];
    __syncthreads();

    // coalesced load of 64 rows x 25 cols; also init out with beta[k]
    #pragma unroll
    for (int i = tid; i < 64 * L_SZ; i += 128) {
        int r = i / L_SZ, c = i - r * L_SZ;
        t[r][c] = x[base * L_SZ + i];
        out[base * L_SZ + i] = sbeta[c];
    }
    __syncthreads();

    // per-column partial sums: group g=tid/32 handles rows g::4
    {
        const int c = tid & 31, g = tid >> 5;
        float s = 0.f, q = 0.f;
        if (c < L_SZ) {
            #pragma unroll
            for (int r = g; r < 64; r += 4) {
                float v = t[r][c];
                s += v;
                q = fmaf(v, v, q);
            }
        }
        ps[g][c] = s;
        pq[g][c] = q;
    }
    __syncthreads();
    if (tid < L_SZ) {
        float S = ps[0][tid] + ps[1][tid] + ps[2][tid] + ps[3][tid];
        float Q = pq[0][tid] + pq[1][tid] + pq[2][tid] + pq[3][tid];
        atomicAdd(&g_sum[tid], S);
        atomicAdd(&g_sumsq[tid], Q);
    }

    // transpose write (coalesced, 64-wide per l)
    #pragma unroll
    for (int i = tid; i < L_SZ * 64; i += 128) {
        int l = i >> 6, r = i & 63;
        g_xT[l * B_SZ + base + r] = t[r][l];
    }
}

// ---------- kernel 2: fused tiny-MLP ensemble (BN applied in-loop) ----------
__global__ void __launch_bounds__(NTHREADS, 5) mlp_kernel(
    const float* __restrict__ gamma, const float* __restrict__ bn_bias,
    const float* __restrict__ W1, const float* __restrict__ b1,
    const float* __restrict__ W2, const float* __restrict__ b2,
    const float* __restrict__ W3, const float* __restrict__ b3,
    const float* __restrict__ W4, const float* __restrict__ b4,
    const float* __restrict__ alpha,
    float* __restrict__ out)
{
    // sized for the 13-l chunk this block processes (~15.7 KB total)
    __shared__ __align__(16) u64 sW1[LCHUNK][8];
    __shared__ __align__(16) u64 sB1[LCHUNK][8];
    __shared__ __align__(16) u64 sW2[LCHUNK][8][8];
    __shared__ __align__(16) u64 sB2[LCHUNK][8];
    __shared__ __align__(16) u64 sW3[LCHUNK][6][8];
    __shared__ u64 sB3[LCHUNK][6];
    __shared__ __align__(16) u64 sW4[LCHUNK][6];   // pre-scaled by alpha[l,k]
    __shared__ u64 sB4[LCHUNK];                    // pre-scaled by alpha[l,k]
    __shared__ u64 sSc[LCHUNK], sSh[LCHUNK];       // BN scale/shift (dup2)

    const int k      = blockIdx.y;
    const int tid    = threadIdx.x;
    const int lstart = blockIdx.z ? 13 : 0;
    const int nl     = blockIdx.z ? 12 : 13;

    {
        const float* p = W1 + (k * L_SZ + lstart) * 8;
        for (int i = tid; i < nl * 8; i += NTHREADS) ((u64*)sW1)[i] = dup2(p[i]);
        p = b1 + (k * L_SZ + lstart) * 8;
        for (int i = tid; i < nl * 8; i += NTHREADS) ((u64*)sB1)[i] = dup2(p[i]);
        p = W2 + (k * L_SZ + lstart) * 64;
        for (int i = tid; i < nl * 64; i += NTHREADS) ((u64*)sW2)[i] = dup2(p[i]);
        p = b2 + (k * L_SZ + lstart) * 8;
        for (int i = tid; i < nl * 8; i += NTHREADS) ((u64*)sB2)[i] = dup2(p[i]);
        p = W3 + (k * L_SZ + lstart) * 48;
        for (int i = tid; i < nl * 48; i += NTHREADS) ((u64*)sW3)[i] = dup2(p[i]);
        p = b3 + (k * L_SZ + lstart) * 6;
        for (int i = tid; i < nl * 6; i += NTHREADS) ((u64*)sB3)[i] = dup2(p[i]);
        p = W4 + (k * L_SZ + lstart) * 6;
        for (int i = tid; i < nl * 6; i += NTHREADS) {
            int gl = lstart + i / 6;
            ((u64*)sW4)[i] = dup2(p[i] * alpha[gl * K_SZ + k]);
        }
        for (int i = tid; i < nl; i += NTHREADS) {
            int gl = lstart + i;
            sB4[i] = dup2(b4[k * L_SZ + gl] * alpha[gl * K_SZ + k]);
            float mean = g_sum[gl] * (1.f / (float)B_SZ);
            float var  = g_sumsq[gl] * (1.f / (float)B_SZ) - mean * mean;
            float s    = gamma[gl] * rsqrtf(var + BN_EPS);
            sSc[i] = dup2(s);
            sSh[i] = dup2(bn_bias[gl] - mean * s);
        }
    }
    __syncthreads();

    const int b0 = (blockIdx.x * NTHREADS + tid) * ROWS_PT;
    u64 accA = 0ULL, accB = 0ULL;

    // software-pipelined x load; pairs load directly as packed u64
    ulonglong2 xv = *(const ulonglong2*)(g_xT + lstart * B_SZ + b0);

    #pragma unroll 1
    for (int li = 0; li < nl; ++li) {
        ulonglong2 xnext;
        if (li + 1 < nl) xnext = *(const ulonglong2*)(g_xT + (lstart + li + 1) * B_SZ + b0);
        u64 scl = sSc[li], shl = sSh[li];
        u64 xnA = ffma2(xv.x, scl, shl);
        u64 xnB = ffma2(xv.y, scl, shl);

        // layer 1: 1 -> 8
        u64 h1A[8], h1B[8];
        {
            const ulonglong2* w  = (const ulonglong2*)sW1[li];
            const ulonglong2* bb = (const ulonglong2*)sB1[li];
            #pragma unroll
            for (int t = 0; t < 4; ++t) {
                ulonglong2 wv = w[t], bv = bb[t];
                h1A[2*t]   = relu2(ffma2(xnA, wv.x, bv.x));
                h1B[2*t]   = relu2(ffma2(xnB, wv.x, bv.x));
                h1A[2*t+1] = relu2(ffma2(xnA, wv.y, bv.y));
                h1B[2*t+1] = relu2(ffma2(xnB, wv.y, bv.y));
            }
        }

        // layer 2: 8 -> 8
        u64 h2A[8], h2B[8];
        #pragma unroll
        for (int i = 0; i < 8; ++i) {
            const ulonglong2* w = (const ulonglong2*)sW2[li][i];
            ulonglong2 w0 = w[0], w1 = w[1], w2 = w[2], w3 = w[3];
            u64 bi = sB2[li][i];
            u64 a = bi, b = bi;
            a = ffma2(h1A[0], w0.x, a); b = ffma2(h1B[0], w0.x, b);
            a = ffma2(h1A[1], w0.y, a); b = ffma2(h1B[1], w0.y, b);
            a = ffma2(h1A[2], w1.x, a); b = ffma2(h1B[2], w1.x, b);
            a = ffma2(h1A[3], w1.y, a); b = ffma2(h1B[3], w1.y, b);
            a = ffma2(h1A[4], w2.x, a); b = ffma2(h1B[4], w2.x, b);
            a = ffma2(h1A[5], w2.y, a); b = ffma2(h1B[5], w2.y, b);
            a = ffma2(h1A[6], w3.x, a); b = ffma2(h1B[6], w3.x, b);
            a = ffma2(h1A[7], w3.y, a); b = ffma2(h1B[7], w3.y, b);
            h2A[i] = relu2(a);
            h2B[i] = relu2(b);
        }

        // layer 3: 8 -> 6
        u64 h3A[6], h3B[6];
        #pragma unroll
        for (int j = 0; j < 6; ++j) {
            const ulonglong2* w = (const ulonglong2*)sW3[li][j];
            ulonglong2 w0 = w[0], w1 = w[1], w2 = w[2], w3 = w[3];
            u64 bj = sB3[li][j];
            u64 a = bj, b = bj;
            a = ffma2(h2A[0], w0.x, a); b = ffma2(h2B[0], w0.x, b);
            a = ffma2(h2A[1], w0.y, a); b = ffma2(h2B[1], w0.y, b);
            a = ffma2(h2A[2], w1.x, a); b = ffma2(h2B[2], w1.x, b);
            a = ffma2(h2A[3], w1.y, a); b = ffma2(h2B[3], w1.y, b);
            a = ffma2(h2A[4], w2.x, a); b = ffma2(h2B[4], w2.x, b);
            a = ffma2(h2A[5], w2.y, a); b = ffma2(h2B[5], w2.y, b);
            a = ffma2(h2A[6], w3.x, a); b = ffma2(h2B[6], w3.x, b);
            a = ffma2(h2A[7], w3.y, a); b = ffma2(h2B[7], w3.y, b);
            h3A[j] = relu2(a);
            h3B[j] = relu2(b);
        }

        // layer 4 (alpha pre-folded)
        u64 fA = sB4[li], fB = sB4[li];
        {
            const ulonglong2* w = (const ulonglong2*)sW4[li];
            ulonglong2 w0 = w[0], w1 = w[1], w2 = w[2];
            fA = ffma2(h3A[0], w0.x, fA); fB = ffma2(h3B[0], w0.x, fB);
            fA = ffma2(h3A[1], w0.y, fA); fB = ffma2(h3B[1], w0.y, fB);
            fA = ffma2(h3A[2], w1.x, fA); fB = ffma2(h3B[2], w1.x, fB);
            fA = ffma2(h3A[3], w1.y, fA); fB = ffma2(h3B[3], w1.y, fB);
            fA = ffma2(h3A[4], w2.x, fA); fB = ffma2(h3B[4], w2.x, fB);
            fA = ffma2(h3A[5], w2.y, fA); fB = ffma2(h3B[5], w2.y, fB);
        }
        accA = add2(accA, fA);
        accB = add2(accB, fB);
        xv = xnext;
    }

    float2 rA = unpack2(accA);
    float2 rB = unpack2(accB);
    atomicAdd(out + (b0 + 0) * K_SZ + k, rA.x);
    atomicAdd(out + (b0 + 1) * K_SZ + k, rA.y);
    atomicAdd(out + (b0 + 2) * K_SZ + k, rB.x);
    atomicAdd(out + (b0 + 3) * K_SZ + k, rB.y);
}

extern "C" void kernel_launch(void* const* d_in, const int* in_sizes, int n_in,
                              void* d_out, int out_size) {
    const float* x      = (const float*)d_in[0];
    const float* gamma  = (const float*)d_in[1];
    const float* bnb    = (const float*)d_in[2];
    const float* W1     = (const float*)d_in[3];
    const float* b1     = (const float*)d_in[4];
    const float* W2     = (const float*)d_in[5];
    const float* b2     = (const float*)d_in[6];
    const float* W3     = (const float*)d_in[7];
    const float* b3     = (const float*)d_in[8];
    const float* W4     = (const float*)d_in[9];
    const float* b4     = (const float*)d_in[10];
    const float* alpha  = (const float*)d_in[11];
    const float* beta   = (const float*)d_in[12];
    float* out = (float*)d_out;

    static int carveout_set = 0;
    if (!carveout_set) {
        cudaFuncSetAttribute(mlp_kernel,
                             cudaFuncAttributePreferredSharedMemoryCarveout, 50);
        carveout_set = 1;
    }

    void* p_sum = nullptr;
    void* p_sq  = nullptr;
    cudaGetSymbolAddress(&p_sum, g_sum);
    cudaGetSymbolAddress(&p_sq,  g_sumsq);
    cudaMemsetAsync(p_sum, 0, L_SZ * sizeof(float));
    cudaMemsetAsync(p_sq,  0, L_SZ * sizeof(float));

    prologue_kernel<<<B_SZ / 64, 128>>>(x, beta, out);
    mlp_kernel<<<dim3(B_SZ / (ROWS_PT * NTHREADS), K_SZ, LSPLIT), NTHREADS>>>(
        gamma, bnb, W1, b1, W2, b2, W3, b3, W4, b4, alpha, out);
}